// round 9
// baseline (speedup 1.0000x reference)
#include <cuda_runtime.h>
#include <cuda_bf16.h>
#include <math.h>

#define BB 32
#define TT 2048
#define FF 512
#define HH 512
#define G4 (4*HH)
#define NGRP 4
#define GCTA 32            // CTAs per group
#define NCTA (NGRP*GCTA)   // 128

typedef unsigned long long u64;

// ---------------- scratch ----------------
__device__ float g_xg[(size_t)TT * BB * G4];   // [T][B][4H]
__device__ float g_hbuf[2][BB * HH];           // ping-pong h
__device__ __align__(128) int g_flag[NGRP * GCTA];  // per-CTA step flags (1 line/group)

// ---------------- packed f32x2 + fast-math helpers ----------------
__device__ __forceinline__ u64 f2dup(float v) {
    u64 r; asm("mov.b64 %0, {%1, %1};" : "=l"(r) : "f"(v)); return r;
}
__device__ __forceinline__ u64 fma2(u64 a, u64 b, u64 c) {
    u64 d; asm("fma.rn.f32x2 %0, %1, %2, %3;" : "=l"(d) : "l"(a), "l"(b), "l"(c)); return d;
}
__device__ __forceinline__ float2 unpack2(u64 v) {
    float2 r; asm("mov.b64 {%0, %1}, %2;" : "=f"(r.x), "=f"(r.y) : "l"(v)); return r;
}
__device__ __forceinline__ float fex2(float x) {
    float r; asm("ex2.approx.f32 %0, %1;" : "=f"(r) : "f"(x)); return r;
}
__device__ __forceinline__ float frcp(float x) {
    float r; asm("rcp.approx.f32 %0, %1;" : "=f"(r) : "f"(x)); return r;
}
#define LOG2E 1.4426950408889634f
__device__ __forceinline__ float fsig(float x) { return frcp(1.f + fex2(-LOG2E * x)); }
__device__ __forceinline__ float ftanh(float x) { return 2.f * frcp(1.f + fex2(-2.f * LOG2E * x)) - 1.f; }

// k4 swizzle: bijection on 0..127; conflict-free for staged stores and dot loads
__device__ __forceinline__ int SWZ(int k4) {
    return (((k4 & 7) << 4) | (k4 >> 3)) ^ (k4 & 7);
}

// ---------------- GEMM: Xg = x @ Wi + bias (occ 2) ----------------
__global__ __launch_bounds__(256, 2) void gemm_xwi(
    const float* __restrict__ x, const float* __restrict__ Wi,
    const float* __restrict__ bias)
{
    __shared__ float asd[2][8][132];
    __shared__ float bsd[2][8][128];

    const int tid = threadIdx.x;
    if (blockIdx.y == 0 && blockIdx.x == 0 && tid < NGRP * GCTA) {
        g_flag[tid] = 0;   // replay-safe flag re-init
    }

    const int tx = tid & 15;
    const int ty = tid >> 4;
    const int row0 = blockIdx.y * 128;
    const int col0 = blockIdx.x * 128;

    const int ar = tid >> 1, ac = tid & 1;
    const int br = tid >> 5, bc = tid & 31;

    const float* aptr = x + (size_t)(row0 + ar) * FF + ac * 4;
    const float* bptr = Wi + (size_t)br * G4 + col0 + bc * 4;

    float4 av = *(const float4*)aptr;
    float4 bv = *(const float4*)bptr;

    u64 acc[8][4];
#pragma unroll
    for (int i = 0; i < 8; i++)
#pragma unroll
        for (int j = 0; j < 4; j++) acc[i][j] = 0ull;

    int p = 0;
    for (int s = 0; s < 64; s++) {
        asd[p][ac * 4 + 0][ar] = av.x;
        asd[p][ac * 4 + 1][ar] = av.y;
        asd[p][ac * 4 + 2][ar] = av.z;
        asd[p][ac * 4 + 3][ar] = av.w;
        *(float4*)&bsd[p][br][bc * 4] = bv;
        __syncthreads();
        if (s < 63) {
            av = *(const float4*)(aptr + (s + 1) * 8);
            bv = *(const float4*)(bptr + (size_t)(s + 1) * 8 * G4);
        }
#pragma unroll
        for (int kk = 0; kk < 8; kk++) {
            float4 a0 = *(const float4*)&asd[p][kk][ty * 8];
            float4 a1 = *(const float4*)&asd[p][kk][ty * 8 + 4];
            const ulonglong2* bp2 = (const ulonglong2*)&bsd[p][kk][tx * 8];
            ulonglong2 r0 = bp2[0], r1 = bp2[1];
            u64 aa[8];
            aa[0] = f2dup(a0.x); aa[1] = f2dup(a0.y);
            aa[2] = f2dup(a0.z); aa[3] = f2dup(a0.w);
            aa[4] = f2dup(a1.x); aa[5] = f2dup(a1.y);
            aa[6] = f2dup(a1.z); aa[7] = f2dup(a1.w);
            u64 bb2[4] = {r0.x, r0.y, r1.x, r1.y};
#pragma unroll
            for (int i = 0; i < 8; i++)
#pragma unroll
                for (int j = 0; j < 4; j++)
                    acc[i][j] = fma2(aa[i], bb2[j], acc[i][j]);
        }
        __syncthreads();
        p ^= 1;
    }

    const int cbase = col0 + tx * 8;
    float4 bia0 = *(const float4*)(bias + cbase);
    float4 bia1 = *(const float4*)(bias + cbase + 4);
#pragma unroll
    for (int i = 0; i < 8; i++) {
        int r = row0 + ty * 8 + i;
        int bidx = r >> 11;
        int t = r & (TT - 1);
        float* dst = g_xg + (size_t)t * (BB * G4) + (size_t)bidx * G4 + cbase;
        float2 p0 = unpack2(acc[i][0]);
        float2 p1 = unpack2(acc[i][1]);
        float2 p2 = unpack2(acc[i][2]);
        float2 p3 = unpack2(acc[i][3]);
        float4 v0, v1;
        v0.x = p0.x + bia0.x; v0.y = p0.y + bia0.y;
        v0.z = p1.x + bia0.z; v0.w = p1.y + bia0.w;
        v1.x = p2.x + bia1.x; v1.y = p2.y + bia1.y;
        v1.z = p3.x + bia1.z; v1.w = p3.y + bia1.w;
        *(float4*)(dst) = v0;
        *(float4*)(dst + 4) = v1;
    }
}

// ---------------- persistent recurrent kernel: 4 independent batch groups ----
#define HS_F4    (8 * 132)                   //  16896 B
#define W_F4     (64 * 132)                  // 135168 B
#define PART_F   (512 * 20)                  //  40960 B
#define SMEM_REC_BYTES (HS_F4 * 16 + W_F4 * 16 + PART_F * 4)

__global__ __launch_bounds__(256, 1) void lstm_rec(
    const float* __restrict__ Wh,
    const float* __restrict__ c0, const float* __restrict__ h0,
    float* __restrict__ out)
{
    extern __shared__ char smraw[];
    float4* hs4  = (float4*)smraw;                           // [8][132]
    float4* wsm4 = (float4*)(smraw + HS_F4 * 16);            // [64][132]
    float*  part = (float*)(smraw + HS_F4 * 16 + W_F4 * 16); // [512][20]

    const int tid = threadIdx.x;
    const int cta = blockIdx.x;
    const int grp = cta >> 5;
    const int cgc = cta & 31;
    const int j0  = cgc * 16;
    const int bG0 = grp * 8;

    // Wh slice -> SMEM (swizzled): 64 cols x 512 k, col c = gate*16 + jj
    {
        float* ws = (float*)wsm4;
        for (int s = tid; s < 32768; s += 256) {
            int kk = s & 3, k4v = (s >> 2) & 127, c = s >> 9;
            int gate = c >> 4, jj = c & 15;
            ws[(c * 132 + SWZ(k4v)) * 4 + kk] =
                Wh[(size_t)(k4v * 4 + kk) * G4 + gate * HH + j0 + jj];
        }
    }

    // dot mapping
    const int kt = tid & 15;
    const int ct = (tid >> 4) & 7;
    const int bt = tid >> 7;
    const int c0i = ct * 8;
    const int b0i = bt * 4;

    // reducer mapping (tid < 128)
    const int b_r  = tid >> 4;
    const int jj_r = tid & 15;
    const int bGr  = bG0 + b_r;
    const int jGr  = j0 + jj_r;

    float creg = 0.f;
    if (tid < 128) creg = c0[bGr * HH + jGr];

    float* outc = out;
    float* outh = out + BB * HH;
    float* ys   = out + 2 * BB * HH;

    int* const myflag  = &g_flag[grp * GCTA + cgc];
    int* const pollptr = (tid < GCTA) ? &g_flag[grp * GCTA + tid] : nullptr;

    for (int t = 0; t < TT; t++) {
        // ---- stage this group's h (8 b x 512): 4 f4 loads/thread ----
        const float4* hsrc = ((t == 0) ? (const float4*)h0 : (const float4*)g_hbuf[t & 1])
                             + bG0 * 128;
#pragma unroll
        for (int m = 0; m < 4; m++) {
            int f4 = tid + m * 256;
            int bb = f4 >> 7;
            int k4 = f4 & 127;
            hs4[bb * 132 + SWZ(k4)] = __ldcv(hsrc + f4);
        }
        float xq0 = 0.f, xq1 = 0.f, xq2 = 0.f, xq3 = 0.f;
        if (tid < 128) {
            const float* xr = g_xg + (size_t)t * (BB * G4) + (size_t)bGr * G4 + jGr;
            xq0 = __ldg(xr);
            xq1 = __ldg(xr + HH);
            xq2 = __ldg(xr + 2 * HH);
            xq3 = __ldg(xr + 3 * HH);
        }
        __syncthreads();

        // ---- dot: 8c x 4b x 32k per thread ----
        u64 acc[8][4];
#pragma unroll
        for (int i = 0; i < 8; i++)
#pragma unroll
            for (int j = 0; j < 4; j++) acc[i][j] = 0ull;

#pragma unroll
        for (int i = 0; i < 8; i++) {
            const int s = i * 16 + (kt ^ i);   // SWZ(kt*8+i)
            ulonglong2 hv[4];
#pragma unroll
            for (int b = 0; b < 4; b++)
                hv[b] = *(const ulonglong2*)(hs4 + (b0i + b) * 132 + s);
            ulonglong2 wv[8];
#pragma unroll
            for (int c = 0; c < 8; c++)
                wv[c] = *(const ulonglong2*)(wsm4 + (c0i + c) * 132 + s);
#pragma unroll
            for (int c = 0; c < 8; c++)
#pragma unroll
                for (int b = 0; b < 4; b++) {
                    acc[c][b] = fma2(hv[b].x, wv[c].x, acc[c][b]);
                    acc[c][b] = fma2(hv[b].y, wv[c].y, acc[c][b]);
                }
        }

#pragma unroll
        for (int c = 0; c < 8; c++)
#pragma unroll
            for (int b = 0; b < 4; b++) {
                float2 uv = unpack2(acc[c][b]);
                part[((b0i + b) * 64 + (c0i + c)) * 20 + kt] = uv.x + uv.y;
            }
        __syncthreads();

        // ---- reduce + activations + h broadcast (tid < 128) ----
        if (tid < 128) {
            float z[4];
#pragma unroll
            for (int g = 0; g < 4; g++) {
                const float* row = part + (b_r * 64 + g * 16 + jj_r) * 20;
                float4 q0 = *(const float4*)(row);
                float4 q1 = *(const float4*)(row + 4);
                float4 q2 = *(const float4*)(row + 8);
                float4 q3 = *(const float4*)(row + 12);
                z[g] = ((q0.x + q0.y) + (q0.z + q0.w))
                     + ((q1.x + q1.y) + (q1.z + q1.w))
                     + ((q2.x + q2.y) + (q2.z + q2.w))
                     + ((q3.x + q3.y) + (q3.z + q3.w));
            }
            float ig = fsig(z[0] + xq0);
            float fg = fsig(z[1] + xq1);
            float gg = ftanh(z[2] + xq2);
            float og = fsig(z[3] + xq3);
            creg = fg * creg + ig * gg;
            float hnew = og * ftanh(creg);
            g_hbuf[(t + 1) & 1][bGr * HH + jGr] = hnew;
            ys[(size_t)bGr * (TT * HH) + (size_t)t * HH + jGr] = hnew;
            if (t == TT - 1) {
                outc[bGr * HH + jGr] = creg;
                outh[bGr * HH + jGr] = hnew;
            }
        }

        // ---- per-group flag-line barrier ----
        __syncthreads();
        if (tid == 0) {
            asm volatile("st.release.gpu.global.s32 [%0], %1;"
                         :: "l"(myflag), "r"(t + 1) : "memory");
        }
        if (tid < GCTA) {
            int v;
            do {
                asm volatile("ld.acquire.gpu.global.s32 %0, [%1];"
                             : "=r"(v) : "l"(pollptr) : "memory");
            } while (v <= t);
        }
        __syncthreads();
    }
}

// ---------------- launcher ----------------
extern "C" void kernel_launch(void* const* d_in, const int* in_sizes, int n_in,
                              void* d_out, int out_size)
{
    const float* x    = (const float*)d_in[0];
    const float* c0   = (const float*)d_in[1];
    const float* h0   = (const float*)d_in[2];
    const float* Wi   = (const float*)d_in[3];
    const float* Wh   = (const float*)d_in[4];
    const float* bias = (const float*)d_in[5];
    float* out = (float*)d_out;

    cudaFuncSetAttribute(lstm_rec, cudaFuncAttributeMaxDynamicSharedMemorySize,
                         SMEM_REC_BYTES);

    gemm_xwi<<<dim3(G4 / 128, (BB * TT) / 128), 256>>>(x, Wi, bias);
    lstm_rec<<<NCTA, 256, SMEM_REC_BYTES>>>(Wh, c0, h0, out);
}

// round 10
// speedup vs baseline: 2.0767x; 2.0767x over previous
#include <cuda_runtime.h>
#include <cuda_bf16.h>
#include <math.h>

#define BB 32
#define TT 2048
#define FF 512
#define HH 512
#define G4 (4*HH)
#define NGRP 4
#define GCTA 32            // CTAs per group
#define NCTA (NGRP*GCTA)   // 128

typedef unsigned long long u64;

// ---------------- scratch ----------------
__device__ float g_xg[(size_t)TT * BB * G4];   // [T][B][4H]
__device__ float g_hbuf[2][BB * HH];           // ping-pong h
__device__ int g_bar[NGRP * TT];               // per-group per-step counters

// ---------------- packed f32x2 + fast-math helpers ----------------
__device__ __forceinline__ u64 f2dup(float v) {
    u64 r; asm("mov.b64 %0, {%1, %1};" : "=l"(r) : "f"(v)); return r;
}
__device__ __forceinline__ u64 fma2(u64 a, u64 b, u64 c) {
    u64 d; asm("fma.rn.f32x2 %0, %1, %2, %3;" : "=l"(d) : "l"(a), "l"(b), "l"(c)); return d;
}
__device__ __forceinline__ float2 unpack2(u64 v) {
    float2 r; asm("mov.b64 {%0, %1}, %2;" : "=f"(r.x), "=f"(r.y) : "l"(v)); return r;
}
__device__ __forceinline__ float fex2(float x) {
    float r; asm("ex2.approx.f32 %0, %1;" : "=f"(r) : "f"(x)); return r;
}
__device__ __forceinline__ float frcp(float x) {
    float r; asm("rcp.approx.f32 %0, %1;" : "=f"(r) : "f"(x)); return r;
}
#define LOG2E 1.4426950408889634f
__device__ __forceinline__ float fsig(float x) { return frcp(1.f + fex2(-LOG2E * x)); }
__device__ __forceinline__ float ftanh(float x) { return 2.f * frcp(1.f + fex2(-2.f * LOG2E * x)) - 1.f; }

// k4 swizzle: bijection on 0..127; conflict-free for staged stores and dot loads
__device__ __forceinline__ int SWZ(int k4) {
    return (((k4 & 7) << 4) | (k4 >> 3)) ^ (k4 & 7);
}

// ---------------- GEMM: Xg = x @ Wi + bias (occ 2) ----------------
__global__ __launch_bounds__(256, 2) void gemm_xwi(
    const float* __restrict__ x, const float* __restrict__ Wi,
    const float* __restrict__ bias)
{
    __shared__ float asd[2][8][132];
    __shared__ float bsd[2][8][128];

    const int tid = threadIdx.x;
    if (blockIdx.y == 0) {   // zero 4*2048 barrier counters (replay safety)
        g_bar[blockIdx.x * 512 + tid] = 0;
        g_bar[blockIdx.x * 512 + 256 + tid] = 0;
    }

    const int tx = tid & 15;
    const int ty = tid >> 4;
    const int row0 = blockIdx.y * 128;
    const int col0 = blockIdx.x * 128;

    const int ar = tid >> 1, ac = tid & 1;
    const int br = tid >> 5, bc = tid & 31;

    const float* aptr = x + (size_t)(row0 + ar) * FF + ac * 4;
    const float* bptr = Wi + (size_t)br * G4 + col0 + bc * 4;

    float4 av = *(const float4*)aptr;
    float4 bv = *(const float4*)bptr;

    u64 acc[8][4];
#pragma unroll
    for (int i = 0; i < 8; i++)
#pragma unroll
        for (int j = 0; j < 4; j++) acc[i][j] = 0ull;

    int p = 0;
    for (int s = 0; s < 64; s++) {
        asd[p][ac * 4 + 0][ar] = av.x;
        asd[p][ac * 4 + 1][ar] = av.y;
        asd[p][ac * 4 + 2][ar] = av.z;
        asd[p][ac * 4 + 3][ar] = av.w;
        *(float4*)&bsd[p][br][bc * 4] = bv;
        __syncthreads();
        if (s < 63) {
            av = *(const float4*)(aptr + (s + 1) * 8);
            bv = *(const float4*)(bptr + (size_t)(s + 1) * 8 * G4);
        }
#pragma unroll
        for (int kk = 0; kk < 8; kk++) {
            float4 a0 = *(const float4*)&asd[p][kk][ty * 8];
            float4 a1 = *(const float4*)&asd[p][kk][ty * 8 + 4];
            const ulonglong2* bp2 = (const ulonglong2*)&bsd[p][kk][tx * 8];
            ulonglong2 r0 = bp2[0], r1 = bp2[1];
            u64 aa[8];
            aa[0] = f2dup(a0.x); aa[1] = f2dup(a0.y);
            aa[2] = f2dup(a0.z); aa[3] = f2dup(a0.w);
            aa[4] = f2dup(a1.x); aa[5] = f2dup(a1.y);
            aa[6] = f2dup(a1.z); aa[7] = f2dup(a1.w);
            u64 bb2[4] = {r0.x, r0.y, r1.x, r1.y};
#pragma unroll
            for (int i = 0; i < 8; i++)
#pragma unroll
                for (int j = 0; j < 4; j++)
                    acc[i][j] = fma2(aa[i], bb2[j], acc[i][j]);
        }
        __syncthreads();
        p ^= 1;
    }

    const int cbase = col0 + tx * 8;
    float4 bia0 = *(const float4*)(bias + cbase);
    float4 bia1 = *(const float4*)(bias + cbase + 4);
#pragma unroll
    for (int i = 0; i < 8; i++) {
        int r = row0 + ty * 8 + i;
        int bidx = r >> 11;
        int t = r & (TT - 1);
        float* dst = g_xg + (size_t)t * (BB * G4) + (size_t)bidx * G4 + cbase;
        float2 p0 = unpack2(acc[i][0]);
        float2 p1 = unpack2(acc[i][1]);
        float2 p2 = unpack2(acc[i][2]);
        float2 p3 = unpack2(acc[i][3]);
        float4 v0, v1;
        v0.x = p0.x + bia0.x; v0.y = p0.y + bia0.y;
        v0.z = p1.x + bia0.z; v0.w = p1.y + bia0.w;
        v1.x = p2.x + bia1.x; v1.y = p2.y + bia1.y;
        v1.z = p3.x + bia1.z; v1.w = p3.y + bia1.w;
        *(float4*)(dst) = v0;
        *(float4*)(dst + 4) = v1;
    }
}

// ---------------- persistent recurrent kernel: 4 independent batch groups ----
// Group (cta>>5) owns 8 batches; CTA (cta&31) owns 16 j's (64 gate-cols).
// Thread tile C=8 x B=4 x K=32; atomic per-group barrier (fan-in 32, tid0 only).
// Epilogue reordered: h store -> sync -> release -> ys/out stores -> poll -> sync.
#define HS_F4    (8 * 132)                   //  16896 B
#define W_F4     (64 * 132)                  // 135168 B
#define PART_F   (512 * 20)                  //  40960 B
#define SMEM_REC_BYTES (HS_F4 * 16 + W_F4 * 16 + PART_F * 4)

__global__ __launch_bounds__(256, 1) void lstm_rec(
    const float* __restrict__ Wh,
    const float* __restrict__ c0, const float* __restrict__ h0,
    float* __restrict__ out)
{
    extern __shared__ char smraw[];
    float4* hs4  = (float4*)smraw;                           // [8][132]
    float4* wsm4 = (float4*)(smraw + HS_F4 * 16);            // [64][132]
    float*  part = (float*)(smraw + HS_F4 * 16 + W_F4 * 16); // [512][20]

    const int tid = threadIdx.x;
    const int cta = blockIdx.x;
    const int grp = cta >> 5;
    const int cgc = cta & 31;
    const int j0  = cgc * 16;
    const int bG0 = grp * 8;

    // Wh slice -> SMEM (swizzled): 64 cols x 512 k, col c = gate*16 + jj
    {
        float* ws = (float*)wsm4;
        for (int s = tid; s < 32768; s += 256) {
            int kk = s & 3, k4v = (s >> 2) & 127, c = s >> 9;
            int gate = c >> 4, jj = c & 15;
            ws[(c * 132 + SWZ(k4v)) * 4 + kk] =
                Wh[(size_t)(k4v * 4 + kk) * G4 + gate * HH + j0 + jj];
        }
    }

    // dot mapping
    const int kt = tid & 15;
    const int ct = (tid >> 4) & 7;
    const int bt = tid >> 7;
    const int c0i = ct * 8;
    const int b0i = bt * 4;

    // reducer mapping (tid < 128)
    const int b_r  = tid >> 4;
    const int jj_r = tid & 15;
    const int bGr  = bG0 + b_r;
    const int jGr  = j0 + jj_r;

    float creg = 0.f;
    if (tid < 128) creg = c0[bGr * HH + jGr];

    float* outc = out;
    float* outh = out + BB * HH;
    float* ys   = out + 2 * BB * HH;

    for (int t = 0; t < TT; t++) {
        // ---- stage this group's h (8 b x 512): 4 f4 loads/thread ----
        const float4* hsrc = ((t == 0) ? (const float4*)h0 : (const float4*)g_hbuf[t & 1])
                             + bG0 * 128;
#pragma unroll
        for (int m = 0; m < 4; m++) {
            int f4 = tid + m * 256;
            int bb = f4 >> 7;
            int k4 = f4 & 127;
            hs4[bb * 132 + SWZ(k4)] = __ldcv(hsrc + f4);
        }
        float xq0 = 0.f, xq1 = 0.f, xq2 = 0.f, xq3 = 0.f;
        if (tid < 128) {
            const float* xr = g_xg + (size_t)t * (BB * G4) + (size_t)bGr * G4 + jGr;
            xq0 = __ldg(xr);
            xq1 = __ldg(xr + HH);
            xq2 = __ldg(xr + 2 * HH);
            xq3 = __ldg(xr + 3 * HH);
        }
        __syncthreads();

        // ---- dot: 8c x 4b x 32k per thread ----
        u64 acc[8][4];
#pragma unroll
        for (int i = 0; i < 8; i++)
#pragma unroll
            for (int j = 0; j < 4; j++) acc[i][j] = 0ull;

#pragma unroll
        for (int i = 0; i < 8; i++) {
            const int s = i * 16 + (kt ^ i);   // SWZ(kt*8+i)
            ulonglong2 hv[4];
#pragma unroll
            for (int b = 0; b < 4; b++)
                hv[b] = *(const ulonglong2*)(hs4 + (b0i + b) * 132 + s);
            ulonglong2 wv[8];
#pragma unroll
            for (int c = 0; c < 8; c++)
                wv[c] = *(const ulonglong2*)(wsm4 + (c0i + c) * 132 + s);
#pragma unroll
            for (int c = 0; c < 8; c++)
#pragma unroll
                for (int b = 0; b < 4; b++) {
                    acc[c][b] = fma2(hv[b].x, wv[c].x, acc[c][b]);
                    acc[c][b] = fma2(hv[b].y, wv[c].y, acc[c][b]);
                }
        }

#pragma unroll
        for (int c = 0; c < 8; c++)
#pragma unroll
            for (int b = 0; b < 4; b++) {
                float2 uv = unpack2(acc[c][b]);
                part[((b0i + b) * 64 + (c0i + c)) * 20 + kt] = uv.x + uv.y;
            }
        __syncthreads();

        // ---- reduce + activations + h store (tid < 128) ----
        float hnew = 0.f;
        if (tid < 128) {
            float z[4];
#pragma unroll
            for (int g = 0; g < 4; g++) {
                const float* row = part + (b_r * 64 + g * 16 + jj_r) * 20;
                float4 q0 = *(const float4*)(row);
                float4 q1 = *(const float4*)(row + 4);
                float4 q2 = *(const float4*)(row + 8);
                float4 q3 = *(const float4*)(row + 12);
                z[g] = ((q0.x + q0.y) + (q0.z + q0.w))
                     + ((q1.x + q1.y) + (q1.z + q1.w))
                     + ((q2.x + q2.y) + (q2.z + q2.w))
                     + ((q3.x + q3.y) + (q3.z + q3.w));
            }
            float ig = fsig(z[0] + xq0);
            float fg = fsig(z[1] + xq1);
            float gg = ftanh(z[2] + xq2);
            float og = fsig(z[3] + xq3);
            creg = fg * creg + ig * gg;
            hnew = og * ftanh(creg);
            g_hbuf[(t + 1) & 1][bGr * HH + jGr] = hnew;   // cross-CTA payload first
        }
        __syncthreads();

        // ---- release early; bulk output stores ride the propagation window ----
        int* const barp = &g_bar[grp * TT + t];
        if (tid == 0) {
            asm volatile("red.release.gpu.global.add.s32 [%0], 1;"
                         :: "l"(barp) : "memory");
        }
        if (tid < 128) {
            ys[(size_t)bGr * (TT * HH) + (size_t)t * HH + jGr] = hnew;
            if (t == TT - 1) {
                outc[bGr * HH + jGr] = creg;
                outh[bGr * HH + jGr] = hnew;
            }
        }
        if (tid == 0) {
            int v;
            do {
                asm volatile("ld.acquire.gpu.global.s32 %0, [%1];"
                             : "=r"(v) : "l"(barp) : "memory");
            } while (v < GCTA);
        }
        __syncthreads();
    }
}

// ---------------- launcher ----------------
extern "C" void kernel_launch(void* const* d_in, const int* in_sizes, int n_in,
                              void* d_out, int out_size)
{
    const float* x    = (const float*)d_in[0];
    const float* c0   = (const float*)d_in[1];
    const float* h0   = (const float*)d_in[2];
    const float* Wi   = (const float*)d_in[3];
    const float* Wh   = (const float*)d_in[4];
    const float* bias = (const float*)d_in[5];
    float* out = (float*)d_out;

    cudaFuncSetAttribute(lstm_rec, cudaFuncAttributeMaxDynamicSharedMemorySize,
                         SMEM_REC_BYTES);

    gemm_xwi<<<dim3(G4 / 128, (BB * TT) / 128), 256>>>(x, Wi, bias);
    lstm_rec<<<NCTA, 256, SMEM_REC_BYTES>>>(Wh, c0, h0, out);
}